// round 4
// baseline (speedup 1.0000x reference)
#include <cuda_runtime.h>
#include <cmath>

// Problem constants
#define S_LEN    2048
#define D_MODEL  1024
#define NHEADS   16
#define DH       64
#define QKV_LD   3072   // 3*D
#define NTOK     4096   // B*S

// Scratch (module-static device globals: allowed, not a runtime alloc)
__device__ float g_qkv[(size_t)NTOK * QKV_LD];   // [tok, h*192 + {q:0-63,k:64-127,v:128-191}]
__device__ float g_attn[(size_t)NTOK * D_MODEL]; // [tok, h*64 + d]

// ---------------------------------------------------------------------------
// SGEMM + bias: C[M,N] = A[M,K] @ B[K,N] + bias[N]
// 128x128 tile, BK=16, 256 threads, 8x8 per-thread micro-tile.
// M%128==0, N%128==0, K%16==0 hold for both call sites -> no bounds checks.
// ---------------------------------------------------------------------------
#define BM 128
#define BN 128
#define BK 16
#define TM 8
#define TN 8

__global__ __launch_bounds__(256, 2)
void sgemm_bias_kernel(const float* __restrict__ A, const float* __restrict__ B,
                       const float* __restrict__ bias, float* __restrict__ C,
                       int M, int N, int K) {
    __shared__ float As[BK][BM + 1];   // +1 pad: conflict-free transposed stores
    __shared__ float Bs[BK][BN];

    const int tid  = threadIdx.x;
    const int trow = tid / (BN / TN);  // 0..15
    const int tcol = tid % (BN / TN);  // 0..15

    const float* Ab = A + (size_t)blockIdx.y * BM * K;
    const float* Bb = B + (size_t)blockIdx.x * BN;

    float acc[TM][TN];
#pragma unroll
    for (int i = 0; i < TM; i++)
#pragma unroll
        for (int j = 0; j < TN; j++) acc[i][j] = 0.f;

    for (int k0 = 0; k0 < K; k0 += BK) {
        // Load A tile (BM x BK), store transposed
        for (int i = tid * 4; i < BM * BK; i += 256 * 4) {
            int row = i / BK, col = i % BK;
            float4 a = *(const float4*)(Ab + (size_t)row * K + k0 + col);
            As[col + 0][row] = a.x;
            As[col + 1][row] = a.y;
            As[col + 2][row] = a.z;
            As[col + 3][row] = a.w;
        }
        // Load B tile (BK x BN)
        for (int i = tid * 4; i < BK * BN; i += 256 * 4) {
            int row = i / BN, col = i % BN;
            *(float4*)(&Bs[row][col]) = *(const float4*)(Bb + (size_t)(k0 + row) * N + col);
        }
        __syncthreads();

#pragma unroll
        for (int kk = 0; kk < BK; kk++) {
            float ar[TM], br[TN];
#pragma unroll
            for (int i = 0; i < TM; i++) ar[i] = As[kk][trow * TM + i];
#pragma unroll
            for (int j = 0; j < TN; j++) br[j] = Bs[kk][tcol * TN + j];
#pragma unroll
            for (int i = 0; i < TM; i++)
#pragma unroll
                for (int j = 0; j < TN; j++) acc[i][j] += ar[i] * br[j];
        }
        __syncthreads();
    }

#pragma unroll
    for (int i = 0; i < TM; i++) {
        int row = blockIdx.y * BM + trow * TM + i;
#pragma unroll
        for (int j = 0; j < TN; j += 4) {
            int col = blockIdx.x * BN + tcol * TN + j;
            float4 v;
            v.x = acc[i][j + 0] + bias[col + 0];
            v.y = acc[i][j + 1] + bias[col + 1];
            v.z = acc[i][j + 2] + bias[col + 2];
            v.w = acc[i][j + 3] + bias[col + 3];
            *(float4*)(C + (size_t)row * N + col) = v;
        }
    }
}

// ---------------------------------------------------------------------------
// Flash attention (causal, online softmax), fp32.
// Block = (q-tile qt, head h, batch b). Bq = Bk = 64, dh = 64.
// 256 threads as 16x16 grid; thread (tr,tc) owns rows tr*4+[0,4) and
// cols/dims tc*4+[0,4). Row-group = 16 consecutive lanes -> shfl reductions.
// Causal: only k-tiles kt <= qt are processed (half the work skipped).
// ---------------------------------------------------------------------------
#define BQ  64
#define BKT 64
#define SLD (DH + 1)   // 65: padded row stride in shared

__global__ __launch_bounds__(256)
void flash_kernel(const float* __restrict__ qkv, float* __restrict__ attn) {
    extern __shared__ float sm[];
    float* Qs = sm;                 // [BQ][SLD]
    float* Ks = Qs + BQ * SLD;      // [BKT][SLD]
    float* Vs = Ks + BKT * SLD;     // [BKT][SLD]
    float* Ps = Vs + BKT * SLD;     // [BQ][SLD]

    const int qt = blockIdx.x, h = blockIdx.y, b = blockIdx.z;
    const int tid = threadIdx.x;
    const int tr = tid / 16, tc = tid % 16;
    const int tokbase = b * S_LEN;
    const float scale = 0.125f;     // 1/sqrt(64)

    // Load Q tile
    for (int i = tid; i < BQ * DH; i += 256) {
        int row = i / DH, col = i % DH;
        Qs[row * SLD + col] =
            qkv[(size_t)(tokbase + qt * BQ + row) * QKV_LD + h * 192 + col];
    }

    float o[4][4];
    float m[4], l[4];
#pragma unroll
    for (int i = 0; i < 4; i++) {
        m[i] = -INFINITY; l[i] = 0.f;
#pragma unroll
        for (int j = 0; j < 4; j++) o[i][j] = 0.f;
    }

    for (int kt = 0; kt <= qt; kt++) {
        __syncthreads();  // protects Qs (1st iter) + Ks/Vs/Ps reuse (later iters)

        // Load K,V tiles
        for (int i = tid; i < BKT * DH; i += 256) {
            int row = i / DH, col = i % DH;
            size_t base = (size_t)(tokbase + kt * BKT + row) * QKV_LD + h * 192;
            Ks[row * SLD + col] = qkv[base + 64 + col];
            Vs[row * SLD + col] = qkv[base + 128 + col];
        }
        __syncthreads();

        // S = Q K^T (4x4 micro-tile)
        float acc[4][4];
#pragma unroll
        for (int i = 0; i < 4; i++)
#pragma unroll
            for (int j = 0; j < 4; j++) acc[i][j] = 0.f;

#pragma unroll 8
        for (int d = 0; d < DH; d++) {
            float a[4], bb[4];
#pragma unroll
            for (int i = 0; i < 4; i++) a[i] = Qs[(tr * 4 + i) * SLD + d];
#pragma unroll
            for (int j = 0; j < 4; j++) bb[j] = Ks[(tc * 4 + j) * SLD + d];
#pragma unroll
            for (int i = 0; i < 4; i++)
#pragma unroll
                for (int j = 0; j < 4; j++) acc[i][j] += a[i] * bb[j];
        }

        // Scale + causal mask (only the diagonal tile needs masking)
        const bool diag = (kt == qt);
#pragma unroll
        for (int i = 0; i < 4; i++)
#pragma unroll
            for (int j = 0; j < 4; j++) {
                acc[i][j] *= scale;
                if (diag && (tc * 4 + j > tr * 4 + i)) acc[i][j] = -INFINITY;
            }

        // Online softmax per row (row spread across 16 lanes, shfl-reduce)
#pragma unroll
        for (int i = 0; i < 4; i++) {
            float mx = fmaxf(fmaxf(acc[i][0], acc[i][1]), fmaxf(acc[i][2], acc[i][3]));
#pragma unroll
            for (int ofs = 1; ofs < 16; ofs <<= 1)
                mx = fmaxf(mx, __shfl_xor_sync(0xffffffffu, mx, ofs));
            float mn = fmaxf(m[i], mx);

            float p[4];
            float ls = 0.f;
#pragma unroll
            for (int j = 0; j < 4; j++) { p[j] = __expf(acc[i][j] - mn); ls += p[j]; }
#pragma unroll
            for (int ofs = 1; ofs < 16; ofs <<= 1)
                ls += __shfl_xor_sync(0xffffffffu, ls, ofs);

            float f = __expf(m[i] - mn);   // = 0 on first tile (m=-inf), harmless
            l[i] = l[i] * f + ls;
            m[i] = mn;
#pragma unroll
            for (int j = 0; j < 4; j++) o[i][j] *= f;
#pragma unroll
            for (int j = 0; j < 4; j++) Ps[(tr * 4 + i) * SLD + tc * 4 + j] = p[j];
        }
        __syncthreads();

        // O += P @ V (4x4 micro-tile)
#pragma unroll 4
        for (int k = 0; k < BKT; k++) {
            float pv[4], vv[4];
#pragma unroll
            for (int i = 0; i < 4; i++) pv[i] = Ps[(tr * 4 + i) * SLD + k];
#pragma unroll
            for (int j = 0; j < 4; j++) vv[j] = Vs[k * SLD + tc * 4 + j];
#pragma unroll
            for (int i = 0; i < 4; i++)
#pragma unroll
                for (int j = 0; j < 4; j++) o[i][j] += pv[i] * vv[j];
        }
    }

    // Normalize and write [B,S,H,dh] -> flat [tok, D]
#pragma unroll
    for (int i = 0; i < 4; i++) {
        float inv = 1.0f / l[i];
#pragma unroll
        for (int j = 0; j < 4; j++) {
            attn[(size_t)(tokbase + qt * BQ + tr * 4 + i) * D_MODEL + h * DH + tc * 4 + j] =
                o[i][j] * inv;
        }
    }
}

// ---------------------------------------------------------------------------
// Launch
// ---------------------------------------------------------------------------
extern "C" void kernel_launch(void* const* d_in, const int* in_sizes, int n_in,
                              void* d_out, int out_size) {
    const float* x    = (const float*)d_in[0];   // [2,2048,1024]
    const float* Wqkv = (const float*)d_in[1];   // [1024,3072]
    const float* bqkv = (const float*)d_in[2];   // [3072]
    const float* Wout = (const float*)d_in[3];   // [1024,1024]
    const float* bout = (const float*)d_in[4];   // [1024]
    float* out = (float*)d_out;                  // [2,2048,1024]

    float* qkv;  cudaGetSymbolAddress((void**)&qkv,  g_qkv);
    float* attn; cudaGetSymbolAddress((void**)&attn, g_attn);

    // Flash kernel needs 66560 B dynamic smem (> 48K default opt-in)
    const int flash_smem = 4 * BQ * SLD * (int)sizeof(float);
    cudaFuncSetAttribute(flash_kernel, cudaFuncAttributeMaxDynamicSharedMemorySize,
                         flash_smem);

    // 1) QKV projection: [4096,1024] @ [1024,3072] + bqkv
    {
        dim3 grid(QKV_LD / BN, NTOK / BM);
        sgemm_bias_kernel<<<grid, 256>>>(x, Wqkv, bqkv, qkv, NTOK, QKV_LD, D_MODEL);
    }

    // 2) Causal flash attention
    {
        dim3 grid(S_LEN / BQ, NHEADS, 2);
        flash_kernel<<<grid, 256, flash_smem>>>(qkv, attn);
    }

    // 3) Output projection: [4096,1024] @ [1024,1024] + bout
    {
        dim3 grid(D_MODEL / BN, NTOK / BM);
        sgemm_bias_kernel<<<grid, 256>>>(attn, Wout, bout, out, NTOK, D_MODEL, D_MODEL);
    }
}

// round 5
// speedup vs baseline: 1.7242x; 1.7242x over previous
#include <cuda_runtime.h>
#include <cmath>

// Problem constants
#define S_LEN    2048
#define D_MODEL  1024
#define NHEADS   16
#define DH       64
#define QKV_LD   3072   // 3*D
#define NTOK     4096   // B*S

// Scratch (module-static device globals: allowed, not a runtime alloc)
__device__ float g_qkv[(size_t)NTOK * QKV_LD];   // [tok, h*192 + {q:0-63,k:64-127,v:128-191}]
__device__ float g_attn[(size_t)NTOK * D_MODEL]; // [tok, h*64 + d]

// ---------------------------------------------------------------------------
// tf32 helpers
// ---------------------------------------------------------------------------
__device__ __forceinline__ unsigned f2tf32(float x) {
    unsigned u;
    asm("cvt.rna.tf32.f32 %0, %1;" : "=r"(u) : "f"(x));
    return u;
}

// D = A@B + C, m16n8k8, A row-major, B col-major, fp32 accum
__device__ __forceinline__ void mma_tf32(float* c, const unsigned* a, const unsigned* b) {
    asm volatile(
        "mma.sync.aligned.m16n8k8.row.col.f32.tf32.tf32.f32 "
        "{%0,%1,%2,%3}, {%4,%5,%6,%7}, {%8,%9}, {%0,%1,%2,%3};"
        : "+f"(c[0]), "+f"(c[1]), "+f"(c[2]), "+f"(c[3])
        : "r"(a[0]), "r"(a[1]), "r"(a[2]), "r"(a[3]), "r"(b[0]), "r"(b[1]));
}

// ---------------------------------------------------------------------------
// tf32 tensor-core GEMM + bias: C[M,N] = A[M,K] @ B[K,N] + bias[N]
// 128x128 CTA tile, BK=32, 256 threads = 8 warps (4x2), warp tile 32x64.
// Per warp: 2 m-tiles x 8 n-tiles of m16n8k8, 4 k-steps per BK iter.
// Smem strides chosen conflict-free for fragment loads:
//   As stride 36 -> bank (4m+k)%32, distinct over lanes
//   Bs stride 136 -> bank (8k+n)%32, distinct over lanes
// M%128==0, N%128==0, K%32==0 at both call sites.
// ---------------------------------------------------------------------------
__global__ __launch_bounds__(256, 2)
void tf32_gemm_bias(const float* __restrict__ A, const float* __restrict__ B,
                    const float* __restrict__ bias, float* __restrict__ C,
                    int M, int N, int K) {
    __shared__ unsigned As[128][36];   // [m][k]
    __shared__ unsigned Bs[32][136];   // [k][n]

    const int tid  = threadIdx.x;
    const int warp = tid >> 5, lane = tid & 31;
    const int gid  = lane >> 2, tig = lane & 3;
    const int wrow = warp >> 1, wcol = warp & 1;
    const int bm = blockIdx.y, bn = blockIdx.x;

    float acc[2][8][4];
#pragma unroll
    for (int mt = 0; mt < 2; mt++)
#pragma unroll
        for (int nt = 0; nt < 8; nt++)
#pragma unroll
            for (int i = 0; i < 4; i++) acc[mt][nt][i] = 0.f;

    for (int k0 = 0; k0 < K; k0 += 32) {
        // Load A tile 128x32 (1024 float4s, 4 per thread), cvt to tf32
#pragma unroll
        for (int c = 0; c < 4; c++) {
            int idx4 = tid + c * 256;
            int row = idx4 >> 3, col = (idx4 & 7) * 4;
            float4 v = *(const float4*)(A + (size_t)(bm * 128 + row) * K + k0 + col);
            As[row][col + 0] = f2tf32(v.x);
            As[row][col + 1] = f2tf32(v.y);
            As[row][col + 2] = f2tf32(v.z);
            As[row][col + 3] = f2tf32(v.w);
        }
        // Load B tile 32x128
#pragma unroll
        for (int c = 0; c < 4; c++) {
            int idx4 = tid + c * 256;
            int row = idx4 >> 5, col = (idx4 & 31) * 4;
            float4 v = *(const float4*)(B + (size_t)(k0 + row) * N + bn * 128 + col);
            Bs[row][col + 0] = f2tf32(v.x);
            Bs[row][col + 1] = f2tf32(v.y);
            Bs[row][col + 2] = f2tf32(v.z);
            Bs[row][col + 3] = f2tf32(v.w);
        }
        __syncthreads();

#pragma unroll
        for (int ks = 0; ks < 4; ks++) {
            const int kk = ks * 8 + tig;
            unsigned af[2][4];
#pragma unroll
            for (int mt = 0; mt < 2; mt++) {
                int m = wrow * 32 + mt * 16 + gid;
                af[mt][0] = As[m][kk];
                af[mt][1] = As[m + 8][kk];
                af[mt][2] = As[m][kk + 4];
                af[mt][3] = As[m + 8][kk + 4];
            }
            unsigned bf[8][2];
#pragma unroll
            for (int nt = 0; nt < 8; nt++) {
                int n = wcol * 64 + nt * 8 + gid;
                bf[nt][0] = Bs[ks * 8 + tig][n];
                bf[nt][1] = Bs[ks * 8 + tig + 4][n];
            }
#pragma unroll
            for (int mt = 0; mt < 2; mt++)
#pragma unroll
                for (int nt = 0; nt < 8; nt++)
                    mma_tf32(acc[mt][nt], af[mt], bf[nt]);
        }
        __syncthreads();
    }

    // Epilogue: bias + store (c0,c1 = row gid cols 2t,2t+1; c2,c3 = row gid+8)
#pragma unroll
    for (int mt = 0; mt < 2; mt++) {
        int row0 = bm * 128 + wrow * 32 + mt * 16 + gid;
#pragma unroll
        for (int nt = 0; nt < 8; nt++) {
            int col = bn * 128 + wcol * 64 + nt * 8 + tig * 2;
            float2 bv = *(const float2*)(bias + col);
            float2 v0 = {acc[mt][nt][0] + bv.x, acc[mt][nt][1] + bv.y};
            float2 v1 = {acc[mt][nt][2] + bv.x, acc[mt][nt][3] + bv.y};
            *(float2*)(C + (size_t)row0 * N + col) = v0;
            *(float2*)(C + (size_t)(row0 + 8) * N + col) = v1;
        }
    }
}

// ---------------------------------------------------------------------------
// Flash attention (causal, online softmax), fp32. UNCHANGED from R3 (validated).
// ---------------------------------------------------------------------------
#define BQ  64
#define BKT 64
#define SLD (DH + 1)   // 65

__global__ __launch_bounds__(256)
void flash_kernel(const float* __restrict__ qkv, float* __restrict__ attn) {
    extern __shared__ float sm[];
    float* Qs = sm;                 // [BQ][SLD]
    float* Ks = Qs + BQ * SLD;      // [BKT][SLD]
    float* Vs = Ks + BKT * SLD;     // [BKT][SLD]
    float* Ps = Vs + BKT * SLD;     // [BQ][SLD]

    const int qt = blockIdx.x, h = blockIdx.y, b = blockIdx.z;
    const int tid = threadIdx.x;
    const int tr = tid / 16, tc = tid % 16;
    const int tokbase = b * S_LEN;
    const float scale = 0.125f;

    for (int i = tid; i < BQ * DH; i += 256) {
        int row = i / DH, col = i % DH;
        Qs[row * SLD + col] =
            qkv[(size_t)(tokbase + qt * BQ + row) * QKV_LD + h * 192 + col];
    }

    float o[4][4];
    float m[4], l[4];
#pragma unroll
    for (int i = 0; i < 4; i++) {
        m[i] = -INFINITY; l[i] = 0.f;
#pragma unroll
        for (int j = 0; j < 4; j++) o[i][j] = 0.f;
    }

    for (int kt = 0; kt <= qt; kt++) {
        __syncthreads();

        for (int i = tid; i < BKT * DH; i += 256) {
            int row = i / DH, col = i % DH;
            size_t base = (size_t)(tokbase + kt * BKT + row) * QKV_LD + h * 192;
            Ks[row * SLD + col] = qkv[base + 64 + col];
            Vs[row * SLD + col] = qkv[base + 128 + col];
        }
        __syncthreads();

        float acc[4][4];
#pragma unroll
        for (int i = 0; i < 4; i++)
#pragma unroll
            for (int j = 0; j < 4; j++) acc[i][j] = 0.f;

#pragma unroll 8
        for (int d = 0; d < DH; d++) {
            float a[4], bb[4];
#pragma unroll
            for (int i = 0; i < 4; i++) a[i] = Qs[(tr * 4 + i) * SLD + d];
#pragma unroll
            for (int j = 0; j < 4; j++) bb[j] = Ks[(tc * 4 + j) * SLD + d];
#pragma unroll
            for (int i = 0; i < 4; i++)
#pragma unroll
                for (int j = 0; j < 4; j++) acc[i][j] += a[i] * bb[j];
        }

        const bool diag = (kt == qt);
#pragma unroll
        for (int i = 0; i < 4; i++)
#pragma unroll
            for (int j = 0; j < 4; j++) {
                acc[i][j] *= scale;
                if (diag && (tc * 4 + j > tr * 4 + i)) acc[i][j] = -INFINITY;
            }

#pragma unroll
        for (int i = 0; i < 4; i++) {
            float mx = fmaxf(fmaxf(acc[i][0], acc[i][1]), fmaxf(acc[i][2], acc[i][3]));
#pragma unroll
            for (int ofs = 1; ofs < 16; ofs <<= 1)
                mx = fmaxf(mx, __shfl_xor_sync(0xffffffffu, mx, ofs));
            float mn = fmaxf(m[i], mx);

            float p[4];
            float ls = 0.f;
#pragma unroll
            for (int j = 0; j < 4; j++) { p[j] = __expf(acc[i][j] - mn); ls += p[j]; }
#pragma unroll
            for (int ofs = 1; ofs < 16; ofs <<= 1)
                ls += __shfl_xor_sync(0xffffffffu, ls, ofs);

            float f = __expf(m[i] - mn);
            l[i] = l[i] * f + ls;
            m[i] = mn;
#pragma unroll
            for (int j = 0; j < 4; j++) o[i][j] *= f;
#pragma unroll
            for (int j = 0; j < 4; j++) Ps[(tr * 4 + i) * SLD + tc * 4 + j] = p[j];
        }
        __syncthreads();

#pragma unroll 4
        for (int k = 0; k < BKT; k++) {
            float pv[4], vv[4];
#pragma unroll
            for (int i = 0; i < 4; i++) pv[i] = Ps[(tr * 4 + i) * SLD + k];
#pragma unroll
            for (int j = 0; j < 4; j++) vv[j] = Vs[k * SLD + tc * 4 + j];
#pragma unroll
            for (int i = 0; i < 4; i++)
#pragma unroll
                for (int j = 0; j < 4; j++) o[i][j] += pv[i] * vv[j];
        }
    }

#pragma unroll
    for (int i = 0; i < 4; i++) {
        float inv = 1.0f / l[i];
#pragma unroll
        for (int j = 0; j < 4; j++) {
            attn[(size_t)(tokbase + qt * BQ + tr * 4 + i) * D_MODEL + h * DH + tc * 4 + j] =
                o[i][j] * inv;
        }
    }
}

// ---------------------------------------------------------------------------
// Launch
// ---------------------------------------------------------------------------
extern "C" void kernel_launch(void* const* d_in, const int* in_sizes, int n_in,
                              void* d_out, int out_size) {
    const float* x    = (const float*)d_in[0];   // [2,2048,1024]
    const float* Wqkv = (const float*)d_in[1];   // [1024,3072]
    const float* bqkv = (const float*)d_in[2];   // [3072]
    const float* Wout = (const float*)d_in[3];   // [1024,1024]
    const float* bout = (const float*)d_in[4];   // [1024]
    float* out = (float*)d_out;                  // [2,2048,1024]

    float* qkv;  cudaGetSymbolAddress((void**)&qkv,  g_qkv);
    float* attn; cudaGetSymbolAddress((void**)&attn, g_attn);

    const int flash_smem = 4 * BQ * SLD * (int)sizeof(float);
    cudaFuncSetAttribute(flash_kernel, cudaFuncAttributeMaxDynamicSharedMemorySize,
                         flash_smem);

    // 1) QKV projection: [4096,1024] @ [1024,3072] + bqkv   (tf32 tensor cores)
    {
        dim3 grid(QKV_LD / 128, NTOK / 128);
        tf32_gemm_bias<<<grid, 256>>>(x, Wqkv, bqkv, qkv, NTOK, QKV_LD, D_MODEL);
    }

    // 2) Causal flash attention (fp32, unchanged)
    {
        dim3 grid(S_LEN / BQ, NHEADS, 2);
        flash_kernel<<<grid, 256, flash_smem>>>(qkv, attn);
    }

    // 3) Output projection: [4096,1024] @ [1024,1024] + bout  (tf32 tensor cores)
    {
        dim3 grid(D_MODEL / 128, NTOK / 128);
        tf32_gemm_bias<<<grid, 256>>>(attn, Wout, bout, out, NTOK, D_MODEL, D_MODEL);
    }
}

// round 6
// speedup vs baseline: 3.2868x; 1.9063x over previous
#include <cuda_runtime.h>
#include <cmath>

// Problem constants
#define S_LEN    2048
#define D_MODEL  1024
#define NHEADS   16
#define DH       64
#define QKV_LD   3072   // 3*D
#define NTOK     4096   // B*S

// Scratch (module-static device globals: allowed, not a runtime alloc)
__device__ float g_qkv[(size_t)NTOK * QKV_LD];   // [tok, h*192 + {q:0-63,k:64-127,v:128-191}]
__device__ float g_attn[(size_t)NTOK * D_MODEL]; // [tok, h*64 + d]

// ---------------------------------------------------------------------------
// tf32 helpers
// ---------------------------------------------------------------------------
__device__ __forceinline__ unsigned f2tf32(float x) {
    unsigned u;
    asm("cvt.rna.tf32.f32 %0, %1;" : "=r"(u) : "f"(x));
    return u;
}

// D += A@B, m16n8k8, A row-major, B col-major, fp32 accum
__device__ __forceinline__ void mma_tf32(float* c, const unsigned* a, const unsigned* b) {
    asm volatile(
        "mma.sync.aligned.m16n8k8.row.col.f32.tf32.tf32.f32 "
        "{%0,%1,%2,%3}, {%4,%5,%6,%7}, {%8,%9}, {%0,%1,%2,%3};"
        : "+f"(c[0]), "+f"(c[1]), "+f"(c[2]), "+f"(c[3])
        : "r"(a[0]), "r"(a[1]), "r"(a[2]), "r"(a[3]), "r"(b[0]), "r"(b[1]));
}

// ---------------------------------------------------------------------------
// tf32 tensor-core GEMM + bias (validated R4, unchanged)
// ---------------------------------------------------------------------------
__global__ __launch_bounds__(256, 2)
void tf32_gemm_bias(const float* __restrict__ A, const float* __restrict__ B,
                    const float* __restrict__ bias, float* __restrict__ C,
                    int M, int N, int K) {
    __shared__ unsigned As[128][36];   // [m][k]
    __shared__ unsigned Bs[32][136];   // [k][n]

    const int tid  = threadIdx.x;
    const int warp = tid >> 5, lane = tid & 31;
    const int gid  = lane >> 2, tig = lane & 3;
    const int wrow = warp >> 1, wcol = warp & 1;
    const int bm = blockIdx.y, bn = blockIdx.x;

    float acc[2][8][4];
#pragma unroll
    for (int mt = 0; mt < 2; mt++)
#pragma unroll
        for (int nt = 0; nt < 8; nt++)
#pragma unroll
            for (int i = 0; i < 4; i++) acc[mt][nt][i] = 0.f;

    for (int k0 = 0; k0 < K; k0 += 32) {
#pragma unroll
        for (int c = 0; c < 4; c++) {
            int idx4 = tid + c * 256;
            int row = idx4 >> 3, col = (idx4 & 7) * 4;
            float4 v = *(const float4*)(A + (size_t)(bm * 128 + row) * K + k0 + col);
            As[row][col + 0] = f2tf32(v.x);
            As[row][col + 1] = f2tf32(v.y);
            As[row][col + 2] = f2tf32(v.z);
            As[row][col + 3] = f2tf32(v.w);
        }
#pragma unroll
        for (int c = 0; c < 4; c++) {
            int idx4 = tid + c * 256;
            int row = idx4 >> 5, col = (idx4 & 31) * 4;
            float4 v = *(const float4*)(B + (size_t)(k0 + row) * N + bn * 128 + col);
            Bs[row][col + 0] = f2tf32(v.x);
            Bs[row][col + 1] = f2tf32(v.y);
            Bs[row][col + 2] = f2tf32(v.z);
            Bs[row][col + 3] = f2tf32(v.w);
        }
        __syncthreads();

#pragma unroll
        for (int ks = 0; ks < 4; ks++) {
            const int kk = ks * 8 + tig;
            unsigned af[2][4];
#pragma unroll
            for (int mt = 0; mt < 2; mt++) {
                int m = wrow * 32 + mt * 16 + gid;
                af[mt][0] = As[m][kk];
                af[mt][1] = As[m + 8][kk];
                af[mt][2] = As[m][kk + 4];
                af[mt][3] = As[m + 8][kk + 4];
            }
            unsigned bf[8][2];
#pragma unroll
            for (int nt = 0; nt < 8; nt++) {
                int n = wcol * 64 + nt * 8 + gid;
                bf[nt][0] = Bs[ks * 8 + tig][n];
                bf[nt][1] = Bs[ks * 8 + tig + 4][n];
            }
#pragma unroll
            for (int mt = 0; mt < 2; mt++)
#pragma unroll
                for (int nt = 0; nt < 8; nt++)
                    mma_tf32(acc[mt][nt], af[mt], bf[nt]);
        }
        __syncthreads();
    }

#pragma unroll
    for (int mt = 0; mt < 2; mt++) {
        int row0 = bm * 128 + wrow * 32 + mt * 16 + gid;
#pragma unroll
        for (int nt = 0; nt < 8; nt++) {
            int col = bn * 128 + wcol * 64 + nt * 8 + tig * 2;
            float2 bv = *(const float2*)(bias + col);
            float2 v0 = {acc[mt][nt][0] + bv.x, acc[mt][nt][1] + bv.y};
            float2 v1 = {acc[mt][nt][2] + bv.x, acc[mt][nt][3] + bv.y};
            *(float2*)(C + (size_t)row0 * N + col) = v0;
            *(float2*)(C + (size_t)(row0 + 8) * N + col) = v1;
        }
    }
}

// ---------------------------------------------------------------------------
// Flash attention with tf32 tensor cores (causal, online softmax).
// CTA = (qtile of 64 rows, head, batch). 4 warps; warp w owns rows w*16..+15.
// QK^T uses 2-term split of Q (q_hi+q_lo, 2 MMAs) -> score error = K-trunc only.
// P is rounded to tf32 BEFORE summing l -> PV normalization self-consistent.
// Smem strides: 68 (bank = 4*gid+tig, conflict-free) for Qh/Ql/Ks/Ps,
//               72 (bank = 8*tig+gid) for Vs.
// ---------------------------------------------------------------------------
#define FQLD 68
#define FVLD 72
// word offsets in dynamic smem (all unsigned words)
#define OFF_QH 0
#define OFF_QL (64 * FQLD)
#define OFF_KS (2 * 64 * FQLD)
#define OFF_VS (3 * 64 * FQLD)
#define OFF_PS (3 * 64 * FQLD + 64 * FVLD)
#define FLASH_SMEM_WORDS (4 * 64 * FQLD + 64 * FVLD)

__global__ __launch_bounds__(128, 2)
void flash_mma_kernel(const float* __restrict__ qkv, float* __restrict__ attn) {
    extern __shared__ unsigned fsm[];
    unsigned* Qh = fsm + OFF_QH;
    unsigned* Ql = fsm + OFF_QL;
    unsigned* Ks = fsm + OFF_KS;
    unsigned* Vs = fsm + OFF_VS;
    unsigned* Ps = fsm + OFF_PS;

    const int qt = gridDim.x - 1 - blockIdx.x;   // heavy tiles first
    const int h = blockIdx.y, b = blockIdx.z;
    const int tid = threadIdx.x;
    const int warp = tid >> 5, lane = tid & 31;
    const int gid = lane >> 2, tig = lane & 3;
    const int m0 = warp * 16;
    const int tokbase = b * S_LEN;
    const float scale = 0.125f;      // 1/sqrt(64)

    // Load Q tile (64x64), split into tf32 hi + lo
#pragma unroll
    for (int c = 0; c < 8; c++) {
        int i = tid + c * 128;       // 1024 float4s
        int row = i >> 4, c4 = (i & 15) << 2;
        const float* src = qkv + (size_t)(tokbase + qt * 64 + row) * QKV_LD + h * 192;
        float4 v = *(const float4*)(src + c4);
        unsigned hx;
        hx = f2tf32(v.x); Qh[row * FQLD + c4 + 0] = hx; Ql[row * FQLD + c4 + 0] = f2tf32(v.x - __uint_as_float(hx));
        hx = f2tf32(v.y); Qh[row * FQLD + c4 + 1] = hx; Ql[row * FQLD + c4 + 1] = f2tf32(v.y - __uint_as_float(hx));
        hx = f2tf32(v.z); Qh[row * FQLD + c4 + 2] = hx; Ql[row * FQLD + c4 + 2] = f2tf32(v.z - __uint_as_float(hx));
        hx = f2tf32(v.w); Qh[row * FQLD + c4 + 3] = hx; Ql[row * FQLD + c4 + 3] = f2tf32(v.w - __uint_as_float(hx));
    }

    float o[8][4];
    float m[2], l[2];
#pragma unroll
    for (int nt = 0; nt < 8; nt++)
#pragma unroll
        for (int i = 0; i < 4; i++) o[nt][i] = 0.f;
    m[0] = m[1] = -INFINITY;
    l[0] = l[1] = 0.f;

    for (int kt = 0; kt <= qt; kt++) {
        __syncthreads();   // prev iter's Ks/Vs reads done (1st iter: Q writes visible)

        // Load K,V tiles (64x64 each), tf32-convert
#pragma unroll
        for (int c = 0; c < 8; c++) {
            int i = tid + c * 128;
            int row = i >> 4, c4 = (i & 15) << 2;
            const float* src = qkv + (size_t)(tokbase + kt * 64 + row) * QKV_LD + h * 192;
            float4 kv = *(const float4*)(src + 64 + c4);
            float4 vv = *(const float4*)(src + 128 + c4);
            Ks[row * FQLD + c4 + 0] = f2tf32(kv.x);
            Ks[row * FQLD + c4 + 1] = f2tf32(kv.y);
            Ks[row * FQLD + c4 + 2] = f2tf32(kv.z);
            Ks[row * FQLD + c4 + 3] = f2tf32(kv.w);
            Vs[row * FVLD + c4 + 0] = f2tf32(vv.x);
            Vs[row * FVLD + c4 + 1] = f2tf32(vv.y);
            Vs[row * FVLD + c4 + 2] = f2tf32(vv.z);
            Vs[row * FVLD + c4 + 3] = f2tf32(vv.w);
        }
        __syncthreads();

        // ---- S = Q K^T (split-Q: 2 MMAs per tile) ----
        float acc[8][4];
#pragma unroll
        for (int nt = 0; nt < 8; nt++)
#pragma unroll
            for (int i = 0; i < 4; i++) acc[nt][i] = 0.f;

#pragma unroll
        for (int ks = 0; ks < 8; ks++) {
            const int kk = ks * 8 + tig;
            unsigned ah[4], al[4];
            ah[0] = Qh[(m0 + gid) * FQLD + kk];
            ah[1] = Qh[(m0 + gid + 8) * FQLD + kk];
            ah[2] = Qh[(m0 + gid) * FQLD + kk + 4];
            ah[3] = Qh[(m0 + gid + 8) * FQLD + kk + 4];
            al[0] = Ql[(m0 + gid) * FQLD + kk];
            al[1] = Ql[(m0 + gid + 8) * FQLD + kk];
            al[2] = Ql[(m0 + gid) * FQLD + kk + 4];
            al[3] = Ql[(m0 + gid + 8) * FQLD + kk + 4];
#pragma unroll
            for (int nt = 0; nt < 8; nt++) {
                unsigned bb[2];
                bb[0] = Ks[(nt * 8 + gid) * FQLD + kk];
                bb[1] = Ks[(nt * 8 + gid) * FQLD + kk + 4];
                mma_tf32(acc[nt], ah, bb);
                mma_tf32(acc[nt], al, bb);
            }
        }

        // ---- scale + causal mask (diag tile only) ----
        const bool diag = (kt == qt);
#pragma unroll
        for (int nt = 0; nt < 8; nt++)
#pragma unroll
            for (int i = 0; i < 4; i++) acc[nt][i] *= scale;
        if (diag) {
            const int i0 = m0 + gid;          // local row for c0,c1
            const int i1 = m0 + gid + 8;      // local row for c2,c3
#pragma unroll
            for (int nt = 0; nt < 8; nt++) {
                int j0 = nt * 8 + 2 * tig, j1 = j0 + 1;
                if (j0 > i0) acc[nt][0] = -INFINITY;
                if (j1 > i0) acc[nt][1] = -INFINITY;
                if (j0 > i1) acc[nt][2] = -INFINITY;
                if (j1 > i1) acc[nt][3] = -INFINITY;
            }
        }

        // ---- online softmax (row spread over 4 tig-lanes) ----
#pragma unroll
        for (int r = 0; r < 2; r++) {
            float mx = -INFINITY;
#pragma unroll
            for (int nt = 0; nt < 8; nt++)
                mx = fmaxf(mx, fmaxf(acc[nt][2 * r], acc[nt][2 * r + 1]));
            mx = fmaxf(mx, __shfl_xor_sync(0xffffffffu, mx, 1));
            mx = fmaxf(mx, __shfl_xor_sync(0xffffffffu, mx, 2));
            float mn = fmaxf(m[r], mx);

            float ls = 0.f;
            const int prow = (m0 + gid + 8 * r) * FQLD;
#pragma unroll
            for (int nt = 0; nt < 8; nt++) {
                float p0 = __expf(acc[nt][2 * r] - mn);
                float p1 = __expf(acc[nt][2 * r + 1] - mn);
                unsigned t0 = f2tf32(p0), t1 = f2tf32(p1);
                ls += __uint_as_float(t0) + __uint_as_float(t1);  // sum the tf32 values
                *(uint2*)(Ps + prow + nt * 8 + 2 * tig) = make_uint2(t0, t1);
            }
            ls += __shfl_xor_sync(0xffffffffu, ls, 1);
            ls += __shfl_xor_sync(0xffffffffu, ls, 2);

            float f = __expf(m[r] - mn);
            l[r] = l[r] * f + ls;
            m[r] = mn;
#pragma unroll
            for (int nt = 0; nt < 8; nt++) {
                o[nt][2 * r] *= f;
                o[nt][2 * r + 1] *= f;
            }
        }
        __syncwarp();   // warp-private Ps visible

        // ---- O += P @ V ----
#pragma unroll
        for (int ks = 0; ks < 8; ks++) {
            const int kk = ks * 8 + tig;
            unsigned a[4];
            a[0] = Ps[(m0 + gid) * FQLD + kk];
            a[1] = Ps[(m0 + gid + 8) * FQLD + kk];
            a[2] = Ps[(m0 + gid) * FQLD + kk + 4];
            a[3] = Ps[(m0 + gid + 8) * FQLD + kk + 4];
#pragma unroll
            for (int nt = 0; nt < 8; nt++) {
                unsigned bb[2];
                bb[0] = Vs[kk * FVLD + nt * 8 + gid];
                bb[1] = Vs[(kk + 4) * FVLD + nt * 8 + gid];
                mma_tf32(o[nt], a, bb);
            }
        }
        __syncwarp();   // Ps reads done before next iter's overwrite
    }

    // ---- normalize + write [tok, h*64+d] ----
    const float inv0 = 1.0f / l[0], inv1 = 1.0f / l[1];
    const int row0 = tokbase + qt * 64 + m0 + gid;
#pragma unroll
    for (int nt = 0; nt < 8; nt++) {
        int col = h * DH + nt * 8 + 2 * tig;
        float2 v0 = {o[nt][0] * inv0, o[nt][1] * inv0};
        float2 v1 = {o[nt][2] * inv1, o[nt][3] * inv1};
        *(float2*)(attn + (size_t)row0 * D_MODEL + col) = v0;
        *(float2*)(attn + (size_t)(row0 + 8) * D_MODEL + col) = v1;
    }
}

// ---------------------------------------------------------------------------
// Launch
// ---------------------------------------------------------------------------
extern "C" void kernel_launch(void* const* d_in, const int* in_sizes, int n_in,
                              void* d_out, int out_size) {
    const float* x    = (const float*)d_in[0];   // [2,2048,1024]
    const float* Wqkv = (const float*)d_in[1];   // [1024,3072]
    const float* bqkv = (const float*)d_in[2];   // [3072]
    const float* Wout = (const float*)d_in[3];   // [1024,1024]
    const float* bout = (const float*)d_in[4];   // [1024]
    float* out = (float*)d_out;                  // [2,2048,1024]

    float* qkv;  cudaGetSymbolAddress((void**)&qkv,  g_qkv);
    float* attn; cudaGetSymbolAddress((void**)&attn, g_attn);

    const int flash_smem = FLASH_SMEM_WORDS * (int)sizeof(unsigned);  // 88064 B
    cudaFuncSetAttribute(flash_mma_kernel, cudaFuncAttributeMaxDynamicSharedMemorySize,
                         flash_smem);

    // 1) QKV projection (tf32 tensor cores)
    {
        dim3 grid(QKV_LD / 128, NTOK / 128);
        tf32_gemm_bias<<<grid, 256>>>(x, Wqkv, bqkv, qkv, NTOK, QKV_LD, D_MODEL);
    }

    // 2) Causal flash attention (tf32 tensor cores)
    {
        dim3 grid(S_LEN / 64, NHEADS, 2);
        flash_mma_kernel<<<grid, 128, flash_smem>>>(qkv, attn);
    }

    // 3) Output projection (tf32 tensor cores)
    {
        dim3 grid(D_MODEL / 128, NTOK / 128);
        tf32_gemm_bias<<<grid, 256>>>(attn, Wout, bout, out, NTOK, D_MODEL, D_MODEL);
    }
}